// round 11
// baseline (speedup 1.0000x reference)
#include <cuda_runtime.h>
#include <cuda_bf16.h>
#include <cuda_fp16.h>
#include <cstdint>

#define NMAX 50000
#define EMAX 850000
#define F 256
#define ALPHA 0.2f

// ---------------------------------------------------------------------------
// Scratch (__device__ globals — allocation-free rule)
// ---------------------------------------------------------------------------
__device__ __half g_hf16[NMAX * F];        // h = x @ W (fp16, gather payload)
__device__ float g_s[NMAX];                // h @ a[:F]
__device__ float g_t[NMAX];                // h @ a[F:]
__device__ __nv_bfloat16 g_wthi[F * F];    // W^T bf16 split ([n][k] K-major)
__device__ __nv_bfloat16 g_wtlo[F * F];
__device__ int g_count[NMAX];
__device__ int g_off[NMAX];
__device__ int g_cursor[NMAX];
__device__ int g_csr_dst[EMAX];
__device__ int g_total;                    // range allocator cursor

// ---------------------------------------------------------------------------
// W transpose + bf16 split, coalesced via 32x32 smem tile. grid (8,8), block (32,8).
// ---------------------------------------------------------------------------
__global__ void convert_w_kernel(const float* __restrict__ W) {
    __shared__ float tile[32][33];
    int k0 = blockIdx.x * 32;
    int n0 = blockIdx.y * 32;
    int tx = threadIdx.x, ty0 = threadIdx.y;
    #pragma unroll
    for (int dy = 0; dy < 32; dy += 8) {
        int ty = ty0 + dy;
        tile[ty][tx] = W[(size_t)(k0 + ty) * F + n0 + tx];
    }
    __syncthreads();
    #pragma unroll
    for (int dy = 0; dy < 32; dy += 8) {
        int ty = ty0 + dy;
        float v = tile[tx][ty];
        __nv_bfloat16 h = __float2bfloat16(v);
        size_t oi = (size_t)(n0 + ty) * F + k0 + tx;
        g_wthi[oi] = h;
        g_wtlo[oi] = __float2bfloat16(v - __bfloat162float(h));
    }
}

// ---------------------------------------------------------------------------
// mma.sync bf16 GEMM: h = x @ W (3-product split), fused s/t epilogue.
// CTA: 128(M) x 256(N), K chunks of 64. 512 threads = 16 warps (4 M x 4 N).
// ---------------------------------------------------------------------------
__device__ __forceinline__ uint32_t smem_u32(const void* p) {
    uint32_t a;
    asm("{ .reg .u64 t; cvta.to.shared.u64 t, %1; cvt.u32.u64 %0, t; }" : "=r"(a) : "l"(p));
    return a;
}

__device__ __forceinline__ void ldsm_x4(uint32_t addr, uint32_t& r0, uint32_t& r1,
                                        uint32_t& r2, uint32_t& r3) {
    asm volatile("ldmatrix.sync.aligned.m8n8.x4.shared.b16 {%0,%1,%2,%3}, [%4];"
                 : "=r"(r0), "=r"(r1), "=r"(r2), "=r"(r3) : "r"(addr));
}

__device__ __forceinline__ void mma_bf16(float* d, const uint32_t* a, uint32_t b0, uint32_t b1) {
    asm volatile("mma.sync.aligned.m16n8k16.row.col.f32.bf16.bf16.f32 "
                 "{%0,%1,%2,%3}, {%4,%5,%6,%7}, {%8,%9}, {%0,%1,%2,%3};"
                 : "+f"(d[0]), "+f"(d[1]), "+f"(d[2]), "+f"(d[3])
                 : "r"(a[0]), "r"(a[1]), "r"(a[2]), "r"(a[3]), "r"(b0), "r"(b1));
}

#define GBM 128
#define GTHR 512
#define ROWB 144
#define SM_SRED 0
#define SM_TRED 512
#define SM_A_HI 1024
#define SM_A_LO (SM_A_HI + 18432)
#define SM_B_HI (SM_A_LO + 18432)
#define SM_B_LO (SM_B_HI + 36864)
#define SM_GEMM_TOTAL (SM_B_LO + 36864)   // 111616

__global__ void __launch_bounds__(GTHR, 1) gemm_mma_kernel(const float* __restrict__ x,
                                                           const float* __restrict__ a, int M) {
    extern __shared__ char smem[];
    const uint32_t sbase = smem_u32(smem);
    const int tid = threadIdx.x;
    const int wid = tid >> 5;
    const int lane = tid & 31;
    const int wm = wid >> 2;
    const int wn = wid & 3;
    const int bm = blockIdx.x * GBM;

    float* s_red = reinterpret_cast<float*>(smem + SM_SRED);
    float* t_red = reinterpret_cast<float*>(smem + SM_TRED);
    if (tid < 128) { s_red[tid] = 0.f; t_red[tid] = 0.f; }

    float acc[2][8][4];
    #pragma unroll
    for (int mf = 0; mf < 2; mf++)
        #pragma unroll
        for (int nf = 0; nf < 8; nf++)
            #pragma unroll
            for (int j = 0; j < 4; j++) acc[mf][nf][j] = 0.f;

    const float4* x4 = reinterpret_cast<const float4*>(x);
    const uint4* whi4 = reinterpret_cast<const uint4*>(g_wthi);
    const uint4* wlo4 = reinterpret_cast<const uint4*>(g_wtlo);

    const int lr = lane & 15;
    const int lc = (lane >> 4) * 16;

    for (int c = 0; c < 4; c++) {
        #pragma unroll
        for (int i = tid; i < 2048; i += GTHR) {
            int row = i >> 4, q = i & 15;
            int grow = bm + row;
            float4 v = make_float4(0.f, 0.f, 0.f, 0.f);
            if (grow < M) v = x4[grow * 64 + c * 16 + q];
            __nv_bfloat162 h0, h1, l0, l1;
            h0.x = __float2bfloat16(v.x); h0.y = __float2bfloat16(v.y);
            h1.x = __float2bfloat16(v.z); h1.y = __float2bfloat16(v.w);
            l0.x = __float2bfloat16(v.x - __bfloat162float(h0.x));
            l0.y = __float2bfloat16(v.y - __bfloat162float(h0.y));
            l1.x = __float2bfloat16(v.z - __bfloat162float(h1.x));
            l1.y = __float2bfloat16(v.w - __bfloat162float(h1.y));
            uint32_t off = (uint32_t)(row * ROWB + q * 8);
            *reinterpret_cast<uint2*>(smem + SM_A_HI + off) =
                make_uint2(*reinterpret_cast<uint32_t*>(&h0), *reinterpret_cast<uint32_t*>(&h1));
            *reinterpret_cast<uint2*>(smem + SM_A_LO + off) =
                make_uint2(*reinterpret_cast<uint32_t*>(&l0), *reinterpret_cast<uint32_t*>(&l1));
        }
        #pragma unroll
        for (int i = tid; i < 2048; i += GTHR) {
            int n = i >> 3, q = i & 7;
            int gi = n * 32 + c * 8 + q;
            *reinterpret_cast<uint4*>(smem + SM_B_HI + n * ROWB + q * 16) = whi4[gi];
            *reinterpret_cast<uint4*>(smem + SM_B_LO + n * ROWB + q * 16) = wlo4[gi];
        }
        __syncthreads();

        #pragma unroll
        for (int ks = 0; ks < 4; ks++) {
            const uint32_t coff = (uint32_t)(ks * 32 + lc);
            uint32_t ah[2][4], al[2][4];
            #pragma unroll
            for (int mf = 0; mf < 2; mf++) {
                uint32_t arow = (uint32_t)(wm * 32 + mf * 16 + lr) * ROWB + coff;
                ldsm_x4(sbase + SM_A_HI + arow, ah[mf][0], ah[mf][1], ah[mf][2], ah[mf][3]);
                ldsm_x4(sbase + SM_A_LO + arow, al[mf][0], al[mf][1], al[mf][2], al[mf][3]);
            }
            #pragma unroll
            for (int nf2 = 0; nf2 < 4; nf2++) {
                uint32_t brow = (uint32_t)(wn * 64 + nf2 * 16 + lr) * ROWB + coff;
                uint32_t bh0, bh1, bh2, bh3, bl0, bl1, bl2, bl3;
                ldsm_x4(sbase + SM_B_HI + brow, bh0, bh1, bh2, bh3);
                ldsm_x4(sbase + SM_B_LO + brow, bl0, bl1, bl2, bl3);
                #pragma unroll
                for (int mf = 0; mf < 2; mf++) {
                    mma_bf16(acc[mf][nf2 * 2 + 0], ah[mf], bh0, bh2);
                    mma_bf16(acc[mf][nf2 * 2 + 0], ah[mf], bl0, bl2);
                    mma_bf16(acc[mf][nf2 * 2 + 0], al[mf], bh0, bh2);
                    mma_bf16(acc[mf][nf2 * 2 + 1], ah[mf], bh1, bh3);
                    mma_bf16(acc[mf][nf2 * 2 + 1], ah[mf], bl1, bl3);
                    mma_bf16(acc[mf][nf2 * 2 + 1], al[mf], bh1, bh3);
                }
            }
        }
        __syncthreads();
    }

    float av[16], atv[16];
    #pragma unroll
    for (int nf = 0; nf < 8; nf++)
        #pragma unroll
        for (int j = 0; j < 2; j++) {
            int col = wn * 64 + nf * 8 + (lane & 3) * 2 + j;
            av[nf * 2 + j] = a[col];
            atv[nf * 2 + j] = a[F + col];
        }

    #pragma unroll
    for (int mf = 0; mf < 2; mf++) {
        #pragma unroll
        for (int rg = 0; rg < 2; rg++) {
            int rloc = wm * 32 + mf * 16 + rg * 8 + (lane >> 2);
            int grow = bm + rloc;
            bool ok = grow < M;
            float sp = 0.f, tp = 0.f;
            #pragma unroll
            for (int nf = 0; nf < 8; nf++) {
                float d0 = acc[mf][nf][rg * 2 + 0];
                float d1 = acc[mf][nf][rg * 2 + 1];
                sp += d0 * av[nf * 2] + d1 * av[nf * 2 + 1];
                tp += d0 * atv[nf * 2] + d1 * atv[nf * 2 + 1];
                if (ok) {
                    int col = wn * 64 + nf * 8 + (lane & 3) * 2;
                    *reinterpret_cast<__half2*>(&g_hf16[(size_t)grow * F + col]) =
                        __floats2half2_rn(d0, d1);
                }
            }
            sp += __shfl_xor_sync(0xFFFFFFFF, sp, 1);
            sp += __shfl_xor_sync(0xFFFFFFFF, sp, 2);
            tp += __shfl_xor_sync(0xFFFFFFFF, tp, 1);
            tp += __shfl_xor_sync(0xFFFFFFFF, tp, 2);
            if ((lane & 3) == 0) {
                atomicAdd(&s_red[rloc], sp);
                atomicAdd(&t_red[rloc], tp);
            }
        }
    }
    __syncthreads();
    if (tid < 128 && bm + tid < M) {
        g_s[bm + tid] = s_red[tid];
        g_t[bm + tid] = t_red[tid];
    }
}

// ---------------------------------------------------------------------------
// CSR build: histogram -> atomic range alloc -> scatter (order-free buckets)
// ---------------------------------------------------------------------------
__global__ void hist_kernel(const int* __restrict__ edge, int E) {
    int i = blockIdx.x * blockDim.x + threadIdx.x;
    if (i < E) atomicAdd(&g_count[edge[i]], 1);
}

__global__ void alloc_kernel(int N) {
    int i = blockIdx.x * blockDim.x + threadIdx.x;
    if (i >= N) return;
    int c = g_count[i];
    int pos = atomicAdd(&g_total, c);   // disjoint ranges; order irrelevant
    g_off[i] = pos;
    g_cursor[i] = pos;
}

__global__ void scatter_kernel(const int* __restrict__ edge, int E) {
    int i = blockIdx.x * blockDim.x + threadIdx.x;
    if (i >= E) return;
    int src = edge[i];
    int dst = edge[E + i];
    int pos = atomicAdd(&g_cursor[src], 1);
    g_csr_dst[pos] = dst;
}

// ---------------------------------------------------------------------------
// Fused aggregation: one WARP per node, 8-deep gather pipeline.
// Lane L owns h columns [L*8, L*8+8) (one uint4 of fp16 per gathered row).
// ---------------------------------------------------------------------------
__global__ void __launch_bounds__(256) agg_kernel(float* __restrict__ out, int N) {
    int warp_id = (blockIdx.x * blockDim.x + threadIdx.x) >> 5;
    int lane = threadIdx.x & 31;
    if (warp_id >= N) return;
    const int node = warp_id;
    const int beg = g_off[node];
    const int deg = g_count[node];
    const float s_src = g_s[node];

    const uint4* hp = reinterpret_cast<const uint4*>(g_hf16);  // 32 uint4 per row
    float acc[8];
    #pragma unroll
    for (int i = 0; i < 8; i++) acc[i] = 0.f;
    float rowsum = 0.f;

    for (int base = 0; base < deg; base += 32) {
        int j = base + lane;
        int d = 0;
        float e = 0.f;
        if (j < deg) {
            d = g_csr_dst[beg + j];
            float logit = s_src + g_t[d];
            float l = logit > 0.f ? logit : ALPHA * logit;
            e = __expf(-l);
            rowsum += e;
        }
        int cnt = min(32, deg - base);
        int cnt_r = (cnt + 7) & ~7;        // pad to x8; pad lanes have e=0, d=0

        for (int k = 0; k < cnt_r; k += 8) {
            int dd[8];
            float ee[8];
            uint4 uu[8];
            #pragma unroll
            for (int q = 0; q < 8; q++) {
                dd[q] = __shfl_sync(0xFFFFFFFF, d, k + q);
                ee[q] = __shfl_sync(0xFFFFFFFF, e, k + q);
            }
            #pragma unroll
            for (int q = 0; q < 8; q++)
                uu[q] = hp[(size_t)dd[q] * 32 + lane];   // 8 LDG.128 in flight
            #pragma unroll
            for (int p = 0; p < 4; p++) {
                #pragma unroll
                for (int q = 0; q < 8; q++) {
                    uint32_t w = (&uu[q].x)[p];
                    float2 f = __half22float2(*reinterpret_cast<__half2*>(&w));
                    acc[p * 2 + 0] += ee[q] * f.x;
                    acc[p * 2 + 1] += ee[q] * f.y;
                }
            }
        }
    }

    #pragma unroll
    for (int off = 16; off > 0; off >>= 1)
        rowsum += __shfl_xor_sync(0xFFFFFFFF, rowsum, off);
    float inv = 1.0f / rowsum;

    float4* dst4 = reinterpret_cast<float4*>(&out[(size_t)node * F + lane * 8]);
    dst4[0] = make_float4(fmaxf(acc[0] * inv, 0.f), fmaxf(acc[1] * inv, 0.f),
                          fmaxf(acc[2] * inv, 0.f), fmaxf(acc[3] * inv, 0.f));
    dst4[1] = make_float4(fmaxf(acc[4] * inv, 0.f), fmaxf(acc[5] * inv, 0.f),
                          fmaxf(acc[6] * inv, 0.f), fmaxf(acc[7] * inv, 0.f));
}

// ---------------------------------------------------------------------------
extern "C" void kernel_launch(void* const* d_in, const int* in_sizes, int n_in,
                              void* d_out, int out_size) {
    const float* x    = (const float*)d_in[0];
    const int*   edge = (const int*)d_in[1];
    const float* W    = (const float*)d_in[2];
    const float* a    = (const float*)d_in[3];
    float* out = (float*)d_out;

    int N = in_sizes[0] / F;
    int E = in_sizes[1] / 2;

    static cudaStream_t s2 = nullptr;
    static cudaEvent_t ev_fork = nullptr, ev_join = nullptr;
    if (!s2) {
        cudaStreamCreateWithFlags(&s2, cudaStreamNonBlocking);
        cudaEventCreateWithFlags(&ev_fork, cudaEventDisableTiming);
        cudaEventCreateWithFlags(&ev_join, cudaEventDisableTiming);
        cudaFuncSetAttribute(gemm_mma_kernel, cudaFuncAttributeMaxDynamicSharedMemorySize,
                             SM_GEMM_TOTAL);
    }

    void *p_count, *p_total;
    cudaGetSymbolAddress(&p_count, g_count);
    cudaGetSymbolAddress(&p_total, g_total);

    cudaEventRecord(ev_fork, 0);
    cudaStreamWaitEvent(s2, ev_fork, 0);

    // --- stream s2: CSR build (memset -> hist -> alloc -> scatter) ---
    cudaMemsetAsync(p_count, 0, (size_t)N * sizeof(int), s2);
    cudaMemsetAsync(p_total, 0, sizeof(int), s2);
    hist_kernel<<<(E + 255) / 256, 256, 0, s2>>>(edge, E);
    alloc_kernel<<<(N + 255) / 256, 256, 0, s2>>>(N);
    scatter_kernel<<<(E + 255) / 256, 256, 0, s2>>>(edge, E);
    cudaEventRecord(ev_join, s2);

    // --- stream 0: GEMM chain ---
    convert_w_kernel<<<dim3(8, 8), dim3(32, 8)>>>(W);
    gemm_mma_kernel<<<(N + GBM - 1) / GBM, GTHR, SM_GEMM_TOTAL>>>(x, a, N);

    // Join, then fused aggregation (one warp per node)
    cudaStreamWaitEvent(0, ev_join, 0);
    agg_kernel<<<(N * 32 + 255) / 256, 256>>>(out, N);
}

// round 13
// speedup vs baseline: 1.0827x; 1.0827x over previous
#include <cuda_runtime.h>
#include <cuda_bf16.h>
#include <cuda_fp16.h>
#include <cstdint>

#define NMAX 50000
#define EMAX 850000
#define F 256
#define ALPHA 0.2f

// ---------------------------------------------------------------------------
// Scratch (__device__ globals — allocation-free rule)
// ---------------------------------------------------------------------------
__device__ __half g_hf16[NMAX * F];        // h = x @ W (fp16, gather payload)
__device__ float g_s[NMAX];                // h @ a[:F]
__device__ float g_t[NMAX];                // h @ a[F:]
__device__ __nv_bfloat16 g_wthi[F * F];    // W^T bf16 split ([n][k] K-major)
__device__ __nv_bfloat16 g_wtlo[F * F];
__device__ int g_count[NMAX];
__device__ int g_off[NMAX];
__device__ int g_cursor[NMAX];
__device__ int g_csr_dst[EMAX];
__device__ int g_total;                    // range allocator cursor

// ---------------------------------------------------------------------------
// W transpose + bf16 split, coalesced via 32x32 smem tile. grid (8,8), block (32,8).
// ---------------------------------------------------------------------------
__global__ void convert_w_kernel(const float* __restrict__ W) {
    __shared__ float tile[32][33];
    int k0 = blockIdx.x * 32;
    int n0 = blockIdx.y * 32;
    int tx = threadIdx.x, ty0 = threadIdx.y;
    #pragma unroll
    for (int dy = 0; dy < 32; dy += 8) {
        int ty = ty0 + dy;
        tile[ty][tx] = W[(size_t)(k0 + ty) * F + n0 + tx];
    }
    __syncthreads();
    #pragma unroll
    for (int dy = 0; dy < 32; dy += 8) {
        int ty = ty0 + dy;
        float v = tile[tx][ty];
        __nv_bfloat16 h = __float2bfloat16(v);
        size_t oi = (size_t)(n0 + ty) * F + k0 + tx;
        g_wthi[oi] = h;
        g_wtlo[oi] = __float2bfloat16(v - __bfloat162float(h));
    }
}

// ---------------------------------------------------------------------------
// mma.sync bf16 GEMM: h = x @ W (3-product split), fused s/t epilogue.
// CTA: 128(M) x 256(N), K chunks of 64. 512 threads = 16 warps (4 M x 4 N).
// A (DRAM) software-pipelined: next chunk prefetched into regs during compute.
// ---------------------------------------------------------------------------
__device__ __forceinline__ uint32_t smem_u32(const void* p) {
    uint32_t a;
    asm("{ .reg .u64 t; cvta.to.shared.u64 t, %1; cvt.u32.u64 %0, t; }" : "=r"(a) : "l"(p));
    return a;
}

__device__ __forceinline__ void ldsm_x4(uint32_t addr, uint32_t& r0, uint32_t& r1,
                                        uint32_t& r2, uint32_t& r3) {
    asm volatile("ldmatrix.sync.aligned.m8n8.x4.shared.b16 {%0,%1,%2,%3}, [%4];"
                 : "=r"(r0), "=r"(r1), "=r"(r2), "=r"(r3) : "r"(addr));
}

__device__ __forceinline__ void mma_bf16(float* d, const uint32_t* a, uint32_t b0, uint32_t b1) {
    asm volatile("mma.sync.aligned.m16n8k16.row.col.f32.bf16.bf16.f32 "
                 "{%0,%1,%2,%3}, {%4,%5,%6,%7}, {%8,%9}, {%0,%1,%2,%3};"
                 : "+f"(d[0]), "+f"(d[1]), "+f"(d[2]), "+f"(d[3])
                 : "r"(a[0]), "r"(a[1]), "r"(a[2]), "r"(a[3]), "r"(b0), "r"(b1));
}

#define GBM 128
#define GTHR 512
#define ROWB 144
#define SM_SRED 0
#define SM_TRED 512
#define SM_A_HI 1024
#define SM_A_LO (SM_A_HI + 18432)
#define SM_B_HI (SM_A_LO + 18432)
#define SM_B_LO (SM_B_HI + 36864)
#define SM_GEMM_TOTAL (SM_B_LO + 36864)   // 111616

__global__ void __launch_bounds__(GTHR, 1) gemm_mma_kernel(const float* __restrict__ x,
                                                           const float* __restrict__ a, int M) {
    extern __shared__ char smem[];
    const uint32_t sbase = smem_u32(smem);
    const int tid = threadIdx.x;
    const int wid = tid >> 5;
    const int lane = tid & 31;
    const int wm = wid >> 2;
    const int wn = wid & 3;
    const int bm = blockIdx.x * GBM;

    float* s_red = reinterpret_cast<float*>(smem + SM_SRED);
    float* t_red = reinterpret_cast<float*>(smem + SM_TRED);
    if (tid < 128) { s_red[tid] = 0.f; t_red[tid] = 0.f; }

    float acc[2][8][4];
    #pragma unroll
    for (int mf = 0; mf < 2; mf++)
        #pragma unroll
        for (int nf = 0; nf < 8; nf++)
            #pragma unroll
            for (int j = 0; j < 4; j++) acc[mf][nf][j] = 0.f;

    const float4* x4 = reinterpret_cast<const float4*>(x);
    const uint4* whi4 = reinterpret_cast<const uint4*>(g_wthi);
    const uint4* wlo4 = reinterpret_cast<const uint4*>(g_wtlo);

    const int lr = lane & 15;
    const int lc = (lane >> 4) * 16;

    // A prefetch state: 4 float4 per thread per chunk (128x64 fp32 / 512 thr)
    const int pr_row = tid >> 4;            // 0..31 base row (x4 groups of 32)
    const int pr_q = tid & 15;
    float4 pfA[4];
    #pragma unroll
    for (int i = 0; i < 4; i++) {
        int row = pr_row + i * 32;
        int grow = bm + row;
        pfA[i] = (grow < M) ? x4[grow * 64 + 0 * 16 + pr_q]
                            : make_float4(0.f, 0.f, 0.f, 0.f);
    }

    for (int c = 0; c < 4; c++) {
        if (c > 0) __syncthreads();        // previous compute done before overwrite

        // store prefetched A with hi/lo split
        #pragma unroll
        for (int i = 0; i < 4; i++) {
            int row = pr_row + i * 32;
            float4 v = pfA[i];
            __nv_bfloat162 h0, h1, l0, l1;
            h0.x = __float2bfloat16(v.x); h0.y = __float2bfloat16(v.y);
            h1.x = __float2bfloat16(v.z); h1.y = __float2bfloat16(v.w);
            l0.x = __float2bfloat16(v.x - __bfloat162float(h0.x));
            l0.y = __float2bfloat16(v.y - __bfloat162float(h0.y));
            l1.x = __float2bfloat16(v.z - __bfloat162float(h1.x));
            l1.y = __float2bfloat16(v.w - __bfloat162float(h1.y));
            uint32_t off = (uint32_t)(row * ROWB + pr_q * 8);
            *reinterpret_cast<uint2*>(smem + SM_A_HI + off) =
                make_uint2(*reinterpret_cast<uint32_t*>(&h0), *reinterpret_cast<uint32_t*>(&h1));
            *reinterpret_cast<uint2*>(smem + SM_A_LO + off) =
                make_uint2(*reinterpret_cast<uint32_t*>(&l0), *reinterpret_cast<uint32_t*>(&l1));
        }
        // stage B (L2-resident)
        #pragma unroll
        for (int i = tid; i < 2048; i += GTHR) {
            int n = i >> 3, q = i & 7;
            int gi = n * 32 + c * 8 + q;
            *reinterpret_cast<uint4*>(smem + SM_B_HI + n * ROWB + q * 16) = whi4[gi];
            *reinterpret_cast<uint4*>(smem + SM_B_LO + n * ROWB + q * 16) = wlo4[gi];
        }
        __syncthreads();

        // prefetch next A chunk (overlaps with mma below)
        if (c < 3) {
            #pragma unroll
            for (int i = 0; i < 4; i++) {
                int row = pr_row + i * 32;
                int grow = bm + row;
                pfA[i] = (grow < M) ? x4[grow * 64 + (c + 1) * 16 + pr_q]
                                    : make_float4(0.f, 0.f, 0.f, 0.f);
            }
        }

        #pragma unroll
        for (int ks = 0; ks < 4; ks++) {
            const uint32_t coff = (uint32_t)(ks * 32 + lc);
            uint32_t ah[2][4], al[2][4];
            #pragma unroll
            for (int mf = 0; mf < 2; mf++) {
                uint32_t arow = (uint32_t)(wm * 32 + mf * 16 + lr) * ROWB + coff;
                ldsm_x4(sbase + SM_A_HI + arow, ah[mf][0], ah[mf][1], ah[mf][2], ah[mf][3]);
                ldsm_x4(sbase + SM_A_LO + arow, al[mf][0], al[mf][1], al[mf][2], al[mf][3]);
            }
            #pragma unroll
            for (int nf2 = 0; nf2 < 4; nf2++) {
                uint32_t brow = (uint32_t)(wn * 64 + nf2 * 16 + lr) * ROWB + coff;
                uint32_t bh0, bh1, bh2, bh3, bl0, bl1, bl2, bl3;
                ldsm_x4(sbase + SM_B_HI + brow, bh0, bh1, bh2, bh3);
                ldsm_x4(sbase + SM_B_LO + brow, bl0, bl1, bl2, bl3);
                #pragma unroll
                for (int mf = 0; mf < 2; mf++) {
                    mma_bf16(acc[mf][nf2 * 2 + 0], ah[mf], bh0, bh2);
                    mma_bf16(acc[mf][nf2 * 2 + 0], ah[mf], bl0, bl2);
                    mma_bf16(acc[mf][nf2 * 2 + 0], al[mf], bh0, bh2);
                    mma_bf16(acc[mf][nf2 * 2 + 1], ah[mf], bh1, bh3);
                    mma_bf16(acc[mf][nf2 * 2 + 1], ah[mf], bl1, bl3);
                    mma_bf16(acc[mf][nf2 * 2 + 1], al[mf], bh1, bh3);
                }
            }
        }
    }
    __syncthreads();

    float av[16], atv[16];
    #pragma unroll
    for (int nf = 0; nf < 8; nf++)
        #pragma unroll
        for (int j = 0; j < 2; j++) {
            int col = wn * 64 + nf * 8 + (lane & 3) * 2 + j;
            av[nf * 2 + j] = a[col];
            atv[nf * 2 + j] = a[F + col];
        }

    #pragma unroll
    for (int mf = 0; mf < 2; mf++) {
        #pragma unroll
        for (int rg = 0; rg < 2; rg++) {
            int rloc = wm * 32 + mf * 16 + rg * 8 + (lane >> 2);
            int grow = bm + rloc;
            bool ok = grow < M;
            float sp = 0.f, tp = 0.f;
            #pragma unroll
            for (int nf = 0; nf < 8; nf++) {
                float d0 = acc[mf][nf][rg * 2 + 0];
                float d1 = acc[mf][nf][rg * 2 + 1];
                sp += d0 * av[nf * 2] + d1 * av[nf * 2 + 1];
                tp += d0 * atv[nf * 2] + d1 * atv[nf * 2 + 1];
                if (ok) {
                    int col = wn * 64 + nf * 8 + (lane & 3) * 2;
                    *reinterpret_cast<__half2*>(&g_hf16[(size_t)grow * F + col]) =
                        __floats2half2_rn(d0, d1);
                }
            }
            sp += __shfl_xor_sync(0xFFFFFFFF, sp, 1);
            sp += __shfl_xor_sync(0xFFFFFFFF, sp, 2);
            tp += __shfl_xor_sync(0xFFFFFFFF, tp, 1);
            tp += __shfl_xor_sync(0xFFFFFFFF, tp, 2);
            if ((lane & 3) == 0) {
                atomicAdd(&s_red[rloc], sp);
                atomicAdd(&t_red[rloc], tp);
            }
        }
    }
    __syncthreads();
    if (tid < 128 && bm + tid < M) {
        g_s[bm + tid] = s_red[tid];
        g_t[bm + tid] = t_red[tid];
    }
}

// ---------------------------------------------------------------------------
// CSR build: histogram -> atomic range alloc -> scatter (order-free buckets)
// ---------------------------------------------------------------------------
__global__ void hist_kernel(const int* __restrict__ edge, int E) {
    int i = blockIdx.x * blockDim.x + threadIdx.x;
    if (i < E) atomicAdd(&g_count[edge[i]], 1);
}

__global__ void alloc_kernel(int N) {
    int i = blockIdx.x * blockDim.x + threadIdx.x;
    if (i >= N) return;
    int c = g_count[i];
    int pos = atomicAdd(&g_total, c);   // disjoint ranges; order irrelevant
    g_off[i] = pos;
    g_cursor[i] = pos;
}

__global__ void scatter_kernel(const int* __restrict__ edge, int E) {
    int i = blockIdx.x * blockDim.x + threadIdx.x;
    if (i >= E) return;
    int src = edge[i];
    int dst = edge[E + i];
    int pos = atomicAdd(&g_cursor[src], 1);
    g_csr_dst[pos] = dst;
}

// ---------------------------------------------------------------------------
// Fused aggregation: one WARP per node, x4 batch (R10-proven shape).
// Lane L owns h columns [L*8, L*8+8) (one uint4 of fp16 per gathered row).
// ---------------------------------------------------------------------------
__global__ void __launch_bounds__(256) agg_kernel(float* __restrict__ out, int N) {
    int warp_id = (blockIdx.x * blockDim.x + threadIdx.x) >> 5;
    int lane = threadIdx.x & 31;
    if (warp_id >= N) return;
    const int node = warp_id;
    const int beg = g_off[node];
    const int deg = g_count[node];
    const float s_src = g_s[node];

    const uint4* hp = reinterpret_cast<const uint4*>(g_hf16);  // 32 uint4 per row
    float acc[8];
    #pragma unroll
    for (int i = 0; i < 8; i++) acc[i] = 0.f;
    float rowsum = 0.f;

    for (int base = 0; base < deg; base += 32) {
        int j = base + lane;
        int d = 0;
        float e = 0.f;
        if (j < deg) {
            d = g_csr_dst[beg + j];
            float logit = s_src + g_t[d];
            float l = logit > 0.f ? logit : ALPHA * logit;
            e = __expf(-l);
            rowsum += e;
        }
        int cnt = min(32, deg - base);
        int cnt_r = (cnt + 3) & ~3;        // pad to x4; pad lanes have e=0, d=0

        for (int k = 0; k < cnt_r; k += 4) {
            int d0 = __shfl_sync(0xFFFFFFFF, d, k + 0);
            int d1 = __shfl_sync(0xFFFFFFFF, d, k + 1);
            int d2 = __shfl_sync(0xFFFFFFFF, d, k + 2);
            int d3 = __shfl_sync(0xFFFFFFFF, d, k + 3);
            float e0 = __shfl_sync(0xFFFFFFFF, e, k + 0);
            float e1 = __shfl_sync(0xFFFFFFFF, e, k + 1);
            float e2 = __shfl_sync(0xFFFFFFFF, e, k + 2);
            float e3 = __shfl_sync(0xFFFFFFFF, e, k + 3);
            uint4 u0 = hp[(size_t)d0 * 32 + lane];
            uint4 u1 = hp[(size_t)d1 * 32 + lane];
            uint4 u2 = hp[(size_t)d2 * 32 + lane];
            uint4 u3 = hp[(size_t)d3 * 32 + lane];
            #pragma unroll
            for (int p = 0; p < 4; p++) {
                uint32_t w0 = (&u0.x)[p], w1 = (&u1.x)[p], w2 = (&u2.x)[p], w3 = (&u3.x)[p];
                float2 f0 = __half22float2(*reinterpret_cast<__half2*>(&w0));
                float2 f1 = __half22float2(*reinterpret_cast<__half2*>(&w1));
                float2 f2 = __half22float2(*reinterpret_cast<__half2*>(&w2));
                float2 f3 = __half22float2(*reinterpret_cast<__half2*>(&w3));
                acc[p * 2 + 0] += e0 * f0.x + e1 * f1.x + e2 * f2.x + e3 * f3.x;
                acc[p * 2 + 1] += e0 * f0.y + e1 * f1.y + e2 * f2.y + e3 * f3.y;
            }
        }
    }

    #pragma unroll
    for (int off = 16; off > 0; off >>= 1)
        rowsum += __shfl_xor_sync(0xFFFFFFFF, rowsum, off);
    float inv = 1.0f / rowsum;

    float4* dst4 = reinterpret_cast<float4*>(&out[(size_t)node * F + lane * 8]);
    dst4[0] = make_float4(fmaxf(acc[0] * inv, 0.f), fmaxf(acc[1] * inv, 0.f),
                          fmaxf(acc[2] * inv, 0.f), fmaxf(acc[3] * inv, 0.f));
    dst4[1] = make_float4(fmaxf(acc[4] * inv, 0.f), fmaxf(acc[5] * inv, 0.f),
                          fmaxf(acc[6] * inv, 0.f), fmaxf(acc[7] * inv, 0.f));
}

// ---------------------------------------------------------------------------
extern "C" void kernel_launch(void* const* d_in, const int* in_sizes, int n_in,
                              void* d_out, int out_size) {
    const float* x    = (const float*)d_in[0];
    const int*   edge = (const int*)d_in[1];
    const float* W    = (const float*)d_in[2];
    const float* a    = (const float*)d_in[3];
    float* out = (float*)d_out;

    int N = in_sizes[0] / F;
    int E = in_sizes[1] / 2;

    static cudaStream_t s2 = nullptr;
    static cudaEvent_t ev_fork = nullptr, ev_join = nullptr;
    if (!s2) {
        cudaStreamCreateWithFlags(&s2, cudaStreamNonBlocking);
        cudaEventCreateWithFlags(&ev_fork, cudaEventDisableTiming);
        cudaEventCreateWithFlags(&ev_join, cudaEventDisableTiming);
        cudaFuncSetAttribute(gemm_mma_kernel, cudaFuncAttributeMaxDynamicSharedMemorySize,
                             SM_GEMM_TOTAL);
    }

    void *p_count, *p_total;
    cudaGetSymbolAddress(&p_count, g_count);
    cudaGetSymbolAddress(&p_total, g_total);

    cudaEventRecord(ev_fork, 0);
    cudaStreamWaitEvent(s2, ev_fork, 0);

    // Submission order chosen so the ncu -s 5 -c 1 capture (6th submitted
    // node, memsets included) lands on gemm_mma_kernel. Events preserve deps.
    cudaMemsetAsync(p_count, 0, (size_t)N * sizeof(int), s2);      // 0
    cudaMemsetAsync(p_total, 0, sizeof(int), s2);                  // 1
    hist_kernel<<<(E + 255) / 256, 256, 0, s2>>>(edge, E);         // 2
    alloc_kernel<<<(N + 255) / 256, 256, 0, s2>>>(N);              // 3
    convert_w_kernel<<<dim3(8, 8), dim3(32, 8)>>>(W);              // 4 (s0)
    gemm_mma_kernel<<<(N + GBM - 1) / GBM, GTHR, SM_GEMM_TOTAL>>>(x, a, N);  // 5 (s0)
    scatter_kernel<<<(E + 255) / 256, 256, 0, s2>>>(edge, E);      // 6 (s2, after alloc)
    cudaEventRecord(ev_join, s2);

    // Join, then fused aggregation (one warp per node)
    cudaStreamWaitEvent(0, ev_join, 0);
    agg_kernel<<<(N * 32 + 255) / 256, 256>>>(out, N);
}